// round 1
// baseline (speedup 1.0000x reference)
#include <cuda_runtime.h>
#include <math.h>

#define BB 16384
#define KK 512

// ---------------- scratch (device globals; no allocations) ----------------
__device__ float g_base_p[BB * 512];
__device__ float g_base_f[BB * 512];
__device__ float g_h1_p[BB * 512];
__device__ float g_h1_f[BB * 512];
__device__ float g_h2_p[BB * 256];
__device__ float g_h2_f[BB * 512];
__device__ float g_pres_state[BB * 6];
__device__ float g_full_state[BB * 12];
__device__ float g_losses[4];  // lf, lp, le, nm

__constant__ int c_perms[6][3] = {
    {0, 1, 2}, {0, 2, 1}, {1, 0, 2}, {1, 2, 0}, {2, 0, 1}, {2, 1, 0}};

__device__ __forceinline__ float gelu_exact(float x) {
    return 0.5f * x * (1.0f + erff(x * 0.7071067811865475f));
}

// ---------------- init: zero states + loss accumulators -------------------
__global__ void init_kernel() {
    int i = blockIdx.x * blockDim.x + threadIdx.x;
    int stride = gridDim.x * blockDim.x;
    const int n = BB * 6 + BB * 12 + 4;
    for (; i < n; i += stride) {
        if (i < BB * 6) g_pres_state[i] = 0.f;
        else if (i < BB * 18) g_full_state[i - BB * 6] = 0.f;
        else g_losses[i - BB * 18] = 0.f;
    }
}

// ---------------- SGEMM: C[BB,N] = A[BB,512] @ W[512,N] + bias ------------
// BM=128, BN=128, BK=16, 256 threads, 8x8 micro-tile (split 4+4).
__global__ __launch_bounds__(256) void sgemm_kernel(
    const float* __restrict__ A, const float* __restrict__ W,
    const float* __restrict__ bias, float* __restrict__ C,
    int N, int do_gelu)
{
    __shared__ float As[16][128];
    __shared__ float Ws[16][128];

    const int tid = threadIdx.x;
    const int brow = blockIdx.y * 128;
    const int bcol = blockIdx.x * 128;

    // global load mapping
    const int ar = tid >> 2;          // 0..63
    const int ac = (tid & 3) << 2;    // 0,4,8,12
    const int wr = tid >> 5;          // 0..7
    const int wc = (tid & 31) << 2;   // 0..124

    // compute mapping: rows {trow..trow+3, trow+64..}, cols {tcol..+3, tcol+64..}
    const int trow = (tid >> 4) << 2; // 0..60
    const int tcol = (tid & 15) << 2; // 0..60

    float acc[8][8];
#pragma unroll
    for (int i = 0; i < 8; i++)
#pragma unroll
        for (int j = 0; j < 8; j++) acc[i][j] = 0.f;

    const float* Aptr = A + (brow + ar) * KK + ac;
    const float* Wptr = W + wr * N + bcol + wc;

    for (int k0 = 0; k0 < KK; k0 += 16) {
        float4 a0 = *(const float4*)(Aptr + k0);
        float4 a1 = *(const float4*)(Aptr + 64 * KK + k0);
        float4 w0 = *(const float4*)(Wptr + k0 * N);
        float4 w1 = *(const float4*)(Wptr + (k0 + 8) * N);

        __syncthreads();
        As[ac + 0][ar] = a0.x; As[ac + 1][ar] = a0.y;
        As[ac + 2][ar] = a0.z; As[ac + 3][ar] = a0.w;
        As[ac + 0][ar + 64] = a1.x; As[ac + 1][ar + 64] = a1.y;
        As[ac + 2][ar + 64] = a1.z; As[ac + 3][ar + 64] = a1.w;
        *(float4*)&Ws[wr][wc] = w0;
        *(float4*)&Ws[wr + 8][wc] = w1;
        __syncthreads();

#pragma unroll
        for (int kk = 0; kk < 16; kk++) {
            float ra[8], rb[8];
            *(float4*)&ra[0] = *(const float4*)&As[kk][trow];
            *(float4*)&ra[4] = *(const float4*)&As[kk][trow + 64];
            *(float4*)&rb[0] = *(const float4*)&Ws[kk][tcol];
            *(float4*)&rb[4] = *(const float4*)&Ws[kk][tcol + 64];
#pragma unroll
            for (int i = 0; i < 8; i++)
#pragma unroll
                for (int j = 0; j < 8; j++)
                    acc[i][j] = fmaf(ra[i], rb[j], acc[i][j]);
        }
    }

    float bv[8];
    *(float4*)&bv[0] = *(const float4*)&bias[bcol + tcol];
    *(float4*)&bv[4] = *(const float4*)&bias[bcol + tcol + 64];

#pragma unroll
    for (int ih = 0; ih < 2; ih++) {
#pragma unroll
        for (int i = 0; i < 4; i++) {
            int r = brow + trow + i + ih * 64;
#pragma unroll
            for (int jh = 0; jh < 2; jh++) {
                float4 v;
                v.x = acc[ih * 4 + i][jh * 4 + 0] + bv[jh * 4 + 0];
                v.y = acc[ih * 4 + i][jh * 4 + 1] + bv[jh * 4 + 1];
                v.z = acc[ih * 4 + i][jh * 4 + 2] + bv[jh * 4 + 2];
                v.w = acc[ih * 4 + i][jh * 4 + 3] + bv[jh * 4 + 3];
                if (do_gelu) {
                    v.x = gelu_exact(v.x); v.y = gelu_exact(v.y);
                    v.z = gelu_exact(v.z); v.w = gelu_exact(v.w);
                }
                *(float4*)&C[r * N + bcol + tcol + jh * 64] = v;
            }
        }
    }
}

// ---------------- build h1 for both branches (per-step corrections) -------
__global__ __launch_bounds__(128) void build_h1_kernel(
    const float* __restrict__ pw1, const float* __restrict__ fw1,
    const int* __restrict__ perm_idx, int step)
{
    const int b = blockIdx.x;
    const int ridx = c_perms[perm_idx[b]][step];

    float ps[6], fs[12];
#pragma unroll
    for (int j = 0; j < 6; j++) ps[j] = g_pres_state[b * 6 + j];
#pragma unroll
    for (int j = 0; j < 12; j++) fs[j] = g_full_state[b * 12 + j];

    const int n = threadIdx.x << 2;  // 4 cols per thread

    // pres branch: rows 512..517 state, 518+ridx one-hot
    float4 hp = *(const float4*)&g_base_p[b * 512 + n];
#pragma unroll
    for (int j = 0; j < 6; j++) {
        float4 w = *(const float4*)&pw1[(512 + j) * 512 + n];
        hp.x = fmaf(ps[j], w.x, hp.x); hp.y = fmaf(ps[j], w.y, hp.y);
        hp.z = fmaf(ps[j], w.z, hp.z); hp.w = fmaf(ps[j], w.w, hp.w);
    }
    {
        float4 w = *(const float4*)&pw1[(518 + ridx) * 512 + n];
        hp.x += w.x; hp.y += w.y; hp.z += w.z; hp.w += w.w;
    }
    hp.x = gelu_exact(hp.x); hp.y = gelu_exact(hp.y);
    hp.z = gelu_exact(hp.z); hp.w = gelu_exact(hp.w);
    *(float4*)&g_h1_p[b * 512 + n] = hp;

    // fe branch: rows 512..523 state, 524+ridx one-hot
    float4 hf = *(const float4*)&g_base_f[b * 512 + n];
#pragma unroll
    for (int j = 0; j < 12; j++) {
        float4 w = *(const float4*)&fw1[(512 + j) * 512 + n];
        hf.x = fmaf(fs[j], w.x, hf.x); hf.y = fmaf(fs[j], w.y, hf.y);
        hf.z = fmaf(fs[j], w.z, hf.z); hf.w = fmaf(fs[j], w.w, hf.w);
    }
    {
        float4 w = *(const float4*)&fw1[(524 + ridx) * 512 + n];
        hf.x += w.x; hf.y += w.y; hf.z += w.z; hf.w += w.w;
    }
    hf.x = gelu_exact(hf.x); hf.y = gelu_exact(hf.y);
    hf.z = gelu_exact(hf.z); hf.w = gelu_exact(hf.w);
    *(float4*)&g_h1_f[b * 512 + n] = hf;
}

// ---------------- head (3rd layer dots) + losses + state update -----------
// one warp per row; 8 rows per block
__global__ __launch_bounds__(256) void head_update_kernel(
    const float* __restrict__ pw3, const float* __restrict__ pb3,
    const float* __restrict__ fw3, const float* __restrict__ fb3,
    const float* __restrict__ freq, const float* __restrict__ pres,
    const float* __restrict__ enrich, const int* __restrict__ perm_idx,
    const int* __restrict__ round_mask, float* __restrict__ out, int step)
{
    __shared__ float blk[4];
    const int tid = threadIdx.x;
    const int lane = tid & 31;
    const int w = tid >> 5;
    if (tid < 4) blk[tid] = 0.f;
    __syncthreads();

    const int b = blockIdx.x * 8 + w;
    float pp = 0.f, pf = 0.f, pe = 0.f;
    const float* hp = g_h2_p + b * 256;
    const float* hf = g_h2_f + b * 512;

#pragma unroll
    for (int m = lane; m < 256; m += 32) pp = fmaf(hp[m], pw3[m], pp);
#pragma unroll
    for (int m = lane; m < 512; m += 32) {
        float v = hf[m];
        float2 f3 = *(const float2*)&fw3[2 * m];
        pf = fmaf(v, f3.x, pf);
        pe = fmaf(v, f3.y, pe);
    }
#pragma unroll
    for (int o = 16; o > 0; o >>= 1) {
        pp += __shfl_xor_sync(0xffffffffu, pp, o);
        pf += __shfl_xor_sync(0xffffffffu, pf, o);
        pe += __shfl_xor_sync(0xffffffffu, pe, o);
    }

    if (lane == 0) {
        pp += pb3[0];
        pf += fb3[0];
        pe += fb3[1];
        const int ridx = c_perms[perm_idx[b]][step];
        const float m = (float)round_mask[b * 3 + ridx];
        const float gt_f = freq[b * 3 + ridx];
        const float gt_p = pres[b * 3 + ridx];
        const float gt_e = enrich[b * 3 + ridx];

        const float dlf = (pf - gt_f) * (pf - gt_f) * m;
        const float bce = fmaxf(pp, 0.f) - pp * gt_p + log1pf(expf(-fabsf(pp)));
        const float dlp = bce * m;
        const float dle = (pe - gt_e) * (pe - gt_e) * m;

        const bool msk = m > 0.5f;
        const float act_f = msk ? fminf(fmaxf(pf, -10.f), 10.f) : gt_f;
        const float act_p = msk ? (1.f / (1.f + expf(-pp))) : gt_p;
        const float act_e = msk ? fminf(fmaxf(pe, -100.f), 100.f) : gt_e;

        g_pres_state[b * 6 + 2 * ridx + 0] = act_p;
        g_pres_state[b * 6 + 2 * ridx + 1] = 1.f;
        g_full_state[b * 12 + 4 * ridx + 0] = act_f;
        g_full_state[b * 12 + 4 * ridx + 1] = act_p;
        g_full_state[b * 12 + 4 * ridx + 2] = act_e;
        g_full_state[b * 12 + 4 * ridx + 3] = 1.f;

        out[3 + b * 3 + ridx] = act_f;
        out[3 + 3 * BB + b * 3 + ridx] = act_p;
        out[3 + 6 * BB + b * 3 + ridx] = act_e;

        atomicAdd(&blk[0], dlf);
        atomicAdd(&blk[1], dlp);
        atomicAdd(&blk[2], dle);
        atomicAdd(&blk[3], m);
    }
    __syncthreads();
    if (tid < 4) atomicAdd(&g_losses[tid], blk[tid]);
}

__global__ void finalize_kernel(float* __restrict__ out) {
    if (threadIdx.x == 0 && blockIdx.x == 0) {
        const float nm = g_losses[3] + 1e-8f;
        out[0] = g_losses[0] / nm;
        out[1] = g_losses[1] / nm;
        out[2] = g_losses[2] / nm;
    }
}

// ---------------- launcher -------------------------------------------------
extern "C" void kernel_launch(void* const* d_in, const int* in_sizes, int n_in,
                              void* d_out, int out_size)
{
    const float* seq      = (const float*)d_in[0];
    const float* freq     = (const float*)d_in[1];
    const float* pres     = (const float*)d_in[2];
    const float* enrich   = (const float*)d_in[3];
    const float* pw1      = (const float*)d_in[4];
    const float* pb1      = (const float*)d_in[5];
    const float* pw2      = (const float*)d_in[6];
    const float* pb2      = (const float*)d_in[7];
    const float* pw3      = (const float*)d_in[8];
    const float* pb3      = (const float*)d_in[9];
    const float* fw1      = (const float*)d_in[10];
    const float* fb1      = (const float*)d_in[11];
    const float* fw2      = (const float*)d_in[12];
    const float* fb2      = (const float*)d_in[13];
    const float* fw3      = (const float*)d_in[14];
    const float* fb3      = (const float*)d_in[15];
    const int*   perm_idx = (const int*)d_in[16];
    const int*   rmask    = (const int*)d_in[17];
    float* out = (float*)d_out;

    float *base_p, *base_f, *h1_p, *h1_f, *h2_p, *h2_f;
    cudaGetSymbolAddress((void**)&base_p, g_base_p);
    cudaGetSymbolAddress((void**)&base_f, g_base_f);
    cudaGetSymbolAddress((void**)&h1_p, g_h1_p);
    cudaGetSymbolAddress((void**)&h1_f, g_h1_f);
    cudaGetSymbolAddress((void**)&h2_p, g_h2_p);
    cudaGetSymbolAddress((void**)&h2_f, g_h2_f);

    init_kernel<<<256, 256>>>();

    // step-invariant base: seq @ W1[:512] + b1 (NO gelu yet)
    sgemm_kernel<<<dim3(4, 128), 256>>>(seq, pw1, pb1, base_p, 512, 0);
    sgemm_kernel<<<dim3(4, 128), 256>>>(seq, fw1, fb1, base_f, 512, 0);

    for (int step = 0; step < 3; step++) {
        build_h1_kernel<<<BB, 128>>>(pw1, fw1, perm_idx, step);
        sgemm_kernel<<<dim3(2, 128), 256>>>(h1_p, pw2, pb2, h2_p, 256, 1);
        sgemm_kernel<<<dim3(4, 128), 256>>>(h1_f, fw2, fb2, h2_f, 512, 1);
        head_update_kernel<<<BB / 8, 256>>>(pw3, pb3, fw3, fb3, freq, pres,
                                            enrich, perm_idx, rmask, out, step);
    }

    finalize_kernel<<<1, 32>>>(out);
}

// round 2
// speedup vs baseline: 1.4316x; 1.4316x over previous
#include <cuda_runtime.h>
#include <math.h>
#include <stdint.h>

#define BB 16384
#define KK 512

// ---------------- scratch (device globals; no allocations) ----------------
__device__ float g_base_p[BB * 512];
__device__ float g_base_f[BB * 512];
__device__ float g_h1_p[BB * 512];
__device__ float g_h1_f[BB * 512];
__device__ float g_h2_p[BB * 256];
__device__ float g_h2_f[BB * 512];
__device__ float g_pres_state[BB * 6];
__device__ float g_full_state[BB * 12];
__device__ float g_losses[4];  // lf, lp, le, nm

__constant__ int c_perms[6][3] = {
    {0, 1, 2}, {0, 2, 1}, {1, 0, 2}, {1, 2, 0}, {2, 0, 1}, {2, 1, 0}};

__device__ __forceinline__ float gelu_exact(float x) {
    return 0.5f * x * (1.0f + erff(x * 0.7071067811865475f));
}

__device__ __forceinline__ float to_tf32(float x) {
    asm("cvt.rna.tf32.f32 %0, %0;" : "+f"(x));
    return x;
}

__device__ __forceinline__ void mma_tf32(float* c, const uint32_t* a,
                                         const uint32_t* b) {
    asm volatile(
        "mma.sync.aligned.m16n8k8.row.col.f32.tf32.tf32.f32 "
        "{%0,%1,%2,%3}, {%4,%5,%6,%7}, {%8,%9}, {%0,%1,%2,%3};"
        : "+f"(c[0]), "+f"(c[1]), "+f"(c[2]), "+f"(c[3])
        : "r"(a[0]), "r"(a[1]), "r"(a[2]), "r"(a[3]), "r"(b[0]), "r"(b[1]));
}

// ---------------- init: zero states + loss accumulators -------------------
__global__ void init_kernel() {
    int i = blockIdx.x * blockDim.x + threadIdx.x;
    int stride = gridDim.x * blockDim.x;
    const int n = BB * 6 + BB * 12 + 4;
    for (; i < n; i += stride) {
        if (i < BB * 6) g_pres_state[i] = 0.f;
        else if (i < BB * 18) g_full_state[i - BB * 6] = 0.f;
        else g_losses[i - BB * 18] = 0.f;
    }
}

// ---------------- TF32 tensor-core GEMM: C = A[BB,512] @ W[512,N] + bias ---
// BM=128, BN=128, BK=16, 256 threads = 8 warps (2x4), warp tile 64x32,
// mma.m16n8k8.tf32, double-buffered smem.
// As padded stride 20 -> A-frag reads hit all 32 banks (conflict-free).
// Bs padded stride 136 -> bank = (8k + n) % 32 (conflict-free).
__global__ __launch_bounds__(256, 2) void mma_gemm_kernel(
    const float* __restrict__ A, const float* __restrict__ W,
    const float* __restrict__ bias, float* __restrict__ C,
    int N, int do_gelu)
{
    __shared__ float As[2][128][20];
    __shared__ float Bs[2][16][136];

    const int tid = threadIdx.x;
    const int lane = tid & 31;
    const int wid = tid >> 5;
    const int warp_m = wid >> 2;   // 0..1
    const int warp_n = wid & 3;    // 0..3
    const int brow = blockIdx.y * 128;
    const int bcol = blockIdx.x * 128;

    // global load mappings
    const int ar = tid >> 2;           // 0..63  (A rows ar, ar+64)
    const int ac = (tid & 3) << 2;     // 0,4,8,12
    const int wr = tid >> 5;           // 0..7   (W rows wr, wr+8)
    const int wc = (tid & 31) << 2;    // 0..124

    const float* Aptr = A + (brow + ar) * KK + ac;
    const float* Wptr = W + wr * N + bcol + wc;

    float acc[4][4][4];
#pragma unroll
    for (int i = 0; i < 4; i++)
#pragma unroll
        for (int j = 0; j < 4; j++)
#pragma unroll
            for (int k = 0; k < 4; k++) acc[i][j][k] = 0.f;

    // prologue: load tile 0
    float4 a0 = *(const float4*)(Aptr);
    float4 a1 = *(const float4*)(Aptr + 64 * KK);
    float4 w0 = *(const float4*)(Wptr);
    float4 w1 = *(const float4*)(Wptr + 8 * N);

    {
        float* as0 = &As[0][ar][ac];
        as0[0] = to_tf32(a0.x); as0[1] = to_tf32(a0.y);
        as0[2] = to_tf32(a0.z); as0[3] = to_tf32(a0.w);
        float* as1 = &As[0][ar + 64][ac];
        as1[0] = to_tf32(a1.x); as1[1] = to_tf32(a1.y);
        as1[2] = to_tf32(a1.z); as1[3] = to_tf32(a1.w);
        float* bs0 = &Bs[0][wr][wc];
        bs0[0] = to_tf32(w0.x); bs0[1] = to_tf32(w0.y);
        bs0[2] = to_tf32(w0.z); bs0[3] = to_tf32(w0.w);
        float* bs1 = &Bs[0][wr + 8][wc];
        bs1[0] = to_tf32(w1.x); bs1[1] = to_tf32(w1.y);
        bs1[2] = to_tf32(w1.z); bs1[3] = to_tf32(w1.w);
    }
    __syncthreads();

    const int a_row0 = warp_m * 64 + (lane >> 2);
    const int a_k = lane & 3;
    const int b_col0 = warp_n * 32 + (lane >> 2);
    const int b_k = lane & 3;

    for (int kt = 0; kt < 32; kt++) {
        const int buf = kt & 1;
        const bool more = (kt < 31);
        if (more) {
            const int k0 = (kt + 1) * 16;
            a0 = *(const float4*)(Aptr + k0);
            a1 = *(const float4*)(Aptr + 64 * KK + k0);
            w0 = *(const float4*)(Wptr + k0 * N);
            w1 = *(const float4*)(Wptr + (k0 + 8) * N);
        }

        // compute on buf
#pragma unroll
        for (int ks = 0; ks < 16; ks += 8) {
            uint32_t af[4][4];
            uint32_t bf[4][2];
#pragma unroll
            for (int mf = 0; mf < 4; mf++) {
                const int r = a_row0 + mf * 16;
                af[mf][0] = __float_as_uint(As[buf][r][ks + a_k]);
                af[mf][1] = __float_as_uint(As[buf][r + 8][ks + a_k]);
                af[mf][2] = __float_as_uint(As[buf][r][ks + a_k + 4]);
                af[mf][3] = __float_as_uint(As[buf][r + 8][ks + a_k + 4]);
            }
#pragma unroll
            for (int nf = 0; nf < 4; nf++) {
                const int cc = b_col0 + nf * 8;
                bf[nf][0] = __float_as_uint(Bs[buf][ks + b_k][cc]);
                bf[nf][1] = __float_as_uint(Bs[buf][ks + b_k + 4][cc]);
            }
#pragma unroll
            for (int mf = 0; mf < 4; mf++)
#pragma unroll
                for (int nf = 0; nf < 4; nf++)
                    mma_tf32(acc[mf][nf], af[mf], bf[nf]);
        }

        if (more) {
            const int nb = buf ^ 1;
            float* as0 = &As[nb][ar][ac];
            as0[0] = to_tf32(a0.x); as0[1] = to_tf32(a0.y);
            as0[2] = to_tf32(a0.z); as0[3] = to_tf32(a0.w);
            float* as1 = &As[nb][ar + 64][ac];
            as1[0] = to_tf32(a1.x); as1[1] = to_tf32(a1.y);
            as1[2] = to_tf32(a1.z); as1[3] = to_tf32(a1.w);
            float* bs0 = &Bs[nb][wr][wc];
            bs0[0] = to_tf32(w0.x); bs0[1] = to_tf32(w0.y);
            bs0[2] = to_tf32(w0.z); bs0[3] = to_tf32(w0.w);
            float* bs1 = &Bs[nb][wr + 8][wc];
            bs1[0] = to_tf32(w1.x); bs1[1] = to_tf32(w1.y);
            bs1[2] = to_tf32(w1.z); bs1[3] = to_tf32(w1.w);
            __syncthreads();
        }
    }

    // epilogue
#pragma unroll
    for (int mf = 0; mf < 4; mf++) {
        const int r0 = brow + warp_m * 64 + mf * 16 + (lane >> 2);
#pragma unroll
        for (int nf = 0; nf < 4; nf++) {
            const int c = bcol + warp_n * 32 + nf * 8 + 2 * (lane & 3);
            const float2 bv = *(const float2*)&bias[c];
            float x0 = acc[mf][nf][0] + bv.x;
            float x1 = acc[mf][nf][1] + bv.y;
            float x2 = acc[mf][nf][2] + bv.x;
            float x3 = acc[mf][nf][3] + bv.y;
            if (do_gelu) {
                x0 = gelu_exact(x0); x1 = gelu_exact(x1);
                x2 = gelu_exact(x2); x3 = gelu_exact(x3);
            }
            float2 v01 = {x0, x1};
            float2 v23 = {x2, x3};
            *(float2*)&C[r0 * N + c] = v01;
            *(float2*)&C[(r0 + 8) * N + c] = v23;
        }
    }
}

// ---------------- build h1 for both branches (per-step corrections) -------
__global__ __launch_bounds__(128) void build_h1_kernel(
    const float* __restrict__ pw1, const float* __restrict__ fw1,
    const int* __restrict__ perm_idx, int step)
{
    const int b = blockIdx.x;
    const int ridx = c_perms[perm_idx[b]][step];

    float ps[6], fs[12];
#pragma unroll
    for (int j = 0; j < 6; j++) ps[j] = g_pres_state[b * 6 + j];
#pragma unroll
    for (int j = 0; j < 12; j++) fs[j] = g_full_state[b * 12 + j];

    const int n = threadIdx.x << 2;  // 4 cols per thread

    // pres branch: rows 512..517 state, 518+ridx one-hot
    float4 hp = *(const float4*)&g_base_p[b * 512 + n];
#pragma unroll
    for (int j = 0; j < 6; j++) {
        float4 w = *(const float4*)&pw1[(512 + j) * 512 + n];
        hp.x = fmaf(ps[j], w.x, hp.x); hp.y = fmaf(ps[j], w.y, hp.y);
        hp.z = fmaf(ps[j], w.z, hp.z); hp.w = fmaf(ps[j], w.w, hp.w);
    }
    {
        float4 w = *(const float4*)&pw1[(518 + ridx) * 512 + n];
        hp.x += w.x; hp.y += w.y; hp.z += w.z; hp.w += w.w;
    }
    hp.x = gelu_exact(hp.x); hp.y = gelu_exact(hp.y);
    hp.z = gelu_exact(hp.z); hp.w = gelu_exact(hp.w);
    *(float4*)&g_h1_p[b * 512 + n] = hp;

    // fe branch: rows 512..523 state, 524+ridx one-hot
    float4 hf = *(const float4*)&g_base_f[b * 512 + n];
#pragma unroll
    for (int j = 0; j < 12; j++) {
        float4 w = *(const float4*)&fw1[(512 + j) * 512 + n];
        hf.x = fmaf(fs[j], w.x, hf.x); hf.y = fmaf(fs[j], w.y, hf.y);
        hf.z = fmaf(fs[j], w.z, hf.z); hf.w = fmaf(fs[j], w.w, hf.w);
    }
    {
        float4 w = *(const float4*)&fw1[(524 + ridx) * 512 + n];
        hf.x += w.x; hf.y += w.y; hf.z += w.z; hf.w += w.w;
    }
    hf.x = gelu_exact(hf.x); hf.y = gelu_exact(hf.y);
    hf.z = gelu_exact(hf.z); hf.w = gelu_exact(hf.w);
    *(float4*)&g_h1_f[b * 512 + n] = hf;
}

// ---------------- head (3rd layer dots) + losses + state update -----------
// one warp per row; 8 rows per block
__global__ __launch_bounds__(256) void head_update_kernel(
    const float* __restrict__ pw3, const float* __restrict__ pb3,
    const float* __restrict__ fw3, const float* __restrict__ fb3,
    const float* __restrict__ freq, const float* __restrict__ pres,
    const float* __restrict__ enrich, const int* __restrict__ perm_idx,
    const int* __restrict__ round_mask, float* __restrict__ out, int step)
{
    __shared__ float blk[4];
    const int tid = threadIdx.x;
    const int lane = tid & 31;
    const int w = tid >> 5;
    if (tid < 4) blk[tid] = 0.f;
    __syncthreads();

    const int b = blockIdx.x * 8 + w;
    float pp = 0.f, pf = 0.f, pe = 0.f;
    const float* hp = g_h2_p + b * 256;
    const float* hf = g_h2_f + b * 512;

#pragma unroll
    for (int m = lane; m < 256; m += 32) pp = fmaf(hp[m], pw3[m], pp);
#pragma unroll
    for (int m = lane; m < 512; m += 32) {
        float v = hf[m];
        float2 f3 = *(const float2*)&fw3[2 * m];
        pf = fmaf(v, f3.x, pf);
        pe = fmaf(v, f3.y, pe);
    }
#pragma unroll
    for (int o = 16; o > 0; o >>= 1) {
        pp += __shfl_xor_sync(0xffffffffu, pp, o);
        pf += __shfl_xor_sync(0xffffffffu, pf, o);
        pe += __shfl_xor_sync(0xffffffffu, pe, o);
    }

    if (lane == 0) {
        pp += pb3[0];
        pf += fb3[0];
        pe += fb3[1];
        const int ridx = c_perms[perm_idx[b]][step];
        const float m = (float)round_mask[b * 3 + ridx];
        const float gt_f = freq[b * 3 + ridx];
        const float gt_p = pres[b * 3 + ridx];
        const float gt_e = enrich[b * 3 + ridx];

        const float dlf = (pf - gt_f) * (pf - gt_f) * m;
        const float bce = fmaxf(pp, 0.f) - pp * gt_p + log1pf(expf(-fabsf(pp)));
        const float dlp = bce * m;
        const float dle = (pe - gt_e) * (pe - gt_e) * m;

        const bool msk = m > 0.5f;
        const float act_f = msk ? fminf(fmaxf(pf, -10.f), 10.f) : gt_f;
        const float act_p = msk ? (1.f / (1.f + expf(-pp))) : gt_p;
        const float act_e = msk ? fminf(fmaxf(pe, -100.f), 100.f) : gt_e;

        g_pres_state[b * 6 + 2 * ridx + 0] = act_p;
        g_pres_state[b * 6 + 2 * ridx + 1] = 1.f;
        g_full_state[b * 12 + 4 * ridx + 0] = act_f;
        g_full_state[b * 12 + 4 * ridx + 1] = act_p;
        g_full_state[b * 12 + 4 * ridx + 2] = act_e;
        g_full_state[b * 12 + 4 * ridx + 3] = 1.f;

        out[3 + b * 3 + ridx] = act_f;
        out[3 + 3 * BB + b * 3 + ridx] = act_p;
        out[3 + 6 * BB + b * 3 + ridx] = act_e;

        atomicAdd(&blk[0], dlf);
        atomicAdd(&blk[1], dlp);
        atomicAdd(&blk[2], dle);
        atomicAdd(&blk[3], m);
    }
    __syncthreads();
    if (tid < 4) atomicAdd(&g_losses[tid], blk[tid]);
}

__global__ void finalize_kernel(float* __restrict__ out) {
    if (threadIdx.x == 0 && blockIdx.x == 0) {
        const float nm = g_losses[3] + 1e-8f;
        out[0] = g_losses[0] / nm;
        out[1] = g_losses[1] / nm;
        out[2] = g_losses[2] / nm;
    }
}

// ---------------- launcher -------------------------------------------------
extern "C" void kernel_launch(void* const* d_in, const int* in_sizes, int n_in,
                              void* d_out, int out_size)
{
    const float* seq      = (const float*)d_in[0];
    const float* freq     = (const float*)d_in[1];
    const float* pres     = (const float*)d_in[2];
    const float* enrich   = (const float*)d_in[3];
    const float* pw1      = (const float*)d_in[4];
    const float* pb1      = (const float*)d_in[5];
    const float* pw2      = (const float*)d_in[6];
    const float* pb2      = (const float*)d_in[7];
    const float* pw3      = (const float*)d_in[8];
    const float* pb3      = (const float*)d_in[9];
    const float* fw1      = (const float*)d_in[10];
    const float* fb1      = (const float*)d_in[11];
    const float* fw2      = (const float*)d_in[12];
    const float* fb2      = (const float*)d_in[13];
    const float* fw3      = (const float*)d_in[14];
    const float* fb3      = (const float*)d_in[15];
    const int*   perm_idx = (const int*)d_in[16];
    const int*   rmask    = (const int*)d_in[17];
    float* out = (float*)d_out;

    float *base_p, *base_f, *h1_p, *h1_f, *h2_p, *h2_f;
    cudaGetSymbolAddress((void**)&base_p, g_base_p);
    cudaGetSymbolAddress((void**)&base_f, g_base_f);
    cudaGetSymbolAddress((void**)&h1_p, g_h1_p);
    cudaGetSymbolAddress((void**)&h1_f, g_h1_f);
    cudaGetSymbolAddress((void**)&h2_p, g_h2_p);
    cudaGetSymbolAddress((void**)&h2_f, g_h2_f);

    init_kernel<<<256, 256>>>();

    // step-invariant base: seq @ W1[:512] + b1 (NO gelu yet)
    mma_gemm_kernel<<<dim3(4, 128), 256>>>(seq, pw1, pb1, base_p, 512, 0);
    mma_gemm_kernel<<<dim3(4, 128), 256>>>(seq, fw1, fb1, base_f, 512, 0);

    for (int step = 0; step < 3; step++) {
        build_h1_kernel<<<BB, 128>>>(pw1, fw1, perm_idx, step);
        mma_gemm_kernel<<<dim3(2, 128), 256>>>(h1_p, pw2, pb2, h2_p, 256, 1);
        mma_gemm_kernel<<<dim3(4, 128), 256>>>(h1_f, fw2, fb2, h2_f, 512, 1);
        head_update_kernel<<<BB / 8, 256>>>(pw3, pb3, fw3, fb3, freq, pres,
                                            enrich, perm_idx, rmask, out, step);
    }

    finalize_kernel<<<1, 32>>>(out);
}

// round 4
// speedup vs baseline: 3.4765x; 2.4284x over previous
#include <cuda_runtime.h>
#include <cuda_fp16.h>
#include <math.h>
#include <stdint.h>

#define BB 16384
#define KK 512

// ---------------- scratch (device globals; no allocations) ----------------
__device__ __half g_seq_h[BB * 512];
__device__ __half g_base_p[BB * 512];
__device__ __half g_base_f[BB * 512];
__device__ __half g_h1_p[BB * 512];
__device__ __half g_h1_f[BB * 512];
__device__ __half g_h2_p[BB * 256];
__device__ __half g_h2_f[BB * 512];
__device__ __half g_wt_p1[512 * 512];   // pw1[0:512]^T  [n][k] fp16
__device__ __half g_wt_f1[512 * 512];   // fw1[0:512]^T
__device__ __half g_wt_p2[256 * 512];   // pw2^T
__device__ __half g_wt_f2[512 * 512];   // fw2^T
__device__ float g_pres_state[BB * 6];
__device__ float g_full_state[BB * 12];
__device__ float g_losses[4];  // lf, lp, le, nm

__constant__ int c_perms[6][3] = {
    {0, 1, 2}, {0, 2, 1}, {1, 0, 2}, {1, 2, 0}, {2, 0, 1}, {2, 1, 0}};

__device__ __forceinline__ float gelu_exact(float x) {
    return 0.5f * x * (1.0f + erff(x * 0.7071067811865475f));
}

// ================= PTX helpers (Ampere-era, safe on sm_103) ================
__device__ __forceinline__ uint32_t smem_u32(const void* p) {
    uint32_t a;
    asm("{ .reg .u64 t; cvta.to.shared.u64 t, %1; cvt.u32.u64 %0, t; }"
        : "=r"(a) : "l"(p));
    return a;
}
__device__ __forceinline__ void cp_async16(uint32_t dst, const void* src) {
    asm volatile("cp.async.ca.shared.global [%0], [%1], 16;" ::"r"(dst),
                 "l"(src) : "memory");
}
#define CP_COMMIT() asm volatile("cp.async.commit_group;" ::: "memory")
#define CP_WAIT(n) asm volatile("cp.async.wait_group %0;" ::"n"(n) : "memory")

__device__ __forceinline__ void ldsm_x4(uint32_t* r, uint32_t addr) {
    asm volatile(
        "ldmatrix.sync.aligned.m8n8.x4.shared.b16 {%0,%1,%2,%3}, [%4];"
        : "=r"(r[0]), "=r"(r[1]), "=r"(r[2]), "=r"(r[3])
        : "r"(addr));
}
__device__ __forceinline__ void mma_f16(float* c, const uint32_t* a,
                                        const uint32_t* b) {
    asm volatile(
        "mma.sync.aligned.m16n8k16.row.col.f32.f16.f16.f32 "
        "{%0,%1,%2,%3}, {%4,%5,%6,%7}, {%8,%9}, {%0,%1,%2,%3};"
        : "+f"(c[0]), "+f"(c[1]), "+f"(c[2]), "+f"(c[3])
        : "r"(a[0]), "r"(a[1]), "r"(a[2]), "r"(a[3]), "r"(b[0]), "r"(b[1]));
}

// ---------------- init ------------------------------------------------------
__global__ void init_kernel() {
    int i = blockIdx.x * blockDim.x + threadIdx.x;
    int stride = gridDim.x * blockDim.x;
    const int n = BB * 6 + BB * 12 + 4;
    for (; i < n; i += stride) {
        if (i < BB * 6) g_pres_state[i] = 0.f;
        else if (i < BB * 18) g_full_state[i - BB * 6] = 0.f;
        else g_losses[i - BB * 18] = 0.f;
    }
}

// ---------------- fp32 -> fp16 convert (seq_embed) --------------------------
__global__ void __launch_bounds__(256) convert_seq_kernel(
    const float* __restrict__ src, __half* __restrict__ dst) {
    const int i = (blockIdx.x * 256 + threadIdx.x) * 8;
    float4 v0 = *(const float4*)(src + i);
    float4 v1 = *(const float4*)(src + i + 4);
    __half2 h[4];
    h[0] = __floats2half2_rn(v0.x, v0.y);
    h[1] = __floats2half2_rn(v0.z, v0.w);
    h[2] = __floats2half2_rn(v1.x, v1.y);
    h[3] = __floats2half2_rn(v1.z, v1.w);
    *(uint4*)(dst + i) = *(uint4*)h;
}

// ---------------- weight transpose+convert: dst[n*512+k]=(half)src[k*N+n] ---
__global__ void transpose_kernel(const float* __restrict__ src,
                                 __half* __restrict__ dst, int N) {
    __shared__ float t[32][33];
    const int n0 = blockIdx.x * 32, k0 = blockIdx.y * 32;
#pragma unroll
    for (int i = 0; i < 4; i++)
        t[threadIdx.y + i * 8][threadIdx.x] =
            src[(k0 + threadIdx.y + i * 8) * N + n0 + threadIdx.x];
    __syncthreads();
#pragma unroll
    for (int i = 0; i < 4; i++)
        dst[(n0 + threadIdx.y + i * 8) * 512 + k0 + threadIdx.x] =
            __float2half_rn(t[threadIdx.x][threadIdx.y + i * 8]);
}

// ---------------- fp16 tensor-core GEMM -------------------------------------
// C[BB,N](fp16) = A[BB,512](fp16) @ Wt^T (Wt [N][512] fp16, K-major) + bias
// BM=128, BN=128, BK=32, 256 threads (8 warps, 2x4), warp tile 64x32.
// cp.async double-buffered; smem rows padded to 80B (conflict-free ldmatrix).
__global__ void __launch_bounds__(256) gemm_h(
    const __half* __restrict__ A, const __half* __restrict__ Wt,
    const float* __restrict__ bias, __half* __restrict__ C,
    int N, int do_gelu)
{
    __shared__ __align__(16) unsigned char sm[40960];
    const uint32_t sb = smem_u32(sm);
    const uint32_t sA[2] = {sb, sb + 10240};
    const uint32_t sB[2] = {sb + 20480, sb + 30720};

    const int tid = threadIdx.x;
    const int lane = tid & 31;
    const int wid = tid >> 5;
    const int warp_m = wid >> 2;   // 0..1
    const int warp_n = wid & 3;    // 0..3
    const int brow = blockIdx.y * 128;
    const int bcol = blockIdx.x * 128;

    const __half* Ab = A + (size_t)brow * 512;
    const __half* Bb = Wt + (size_t)bcol * 512;

    const int lr = tid >> 1;              // rows covered twice below
    (void)lr;

    float acc[4][4][4];
#pragma unroll
    for (int i = 0; i < 4; i++)
#pragma unroll
        for (int j = 0; j < 4; j++)
#pragma unroll
            for (int k = 0; k < 4; k++) acc[i][j][k] = 0.f;

    // tile loader: 128 rows x 32 fp16 = 512 x 16B chunks each for A and B
#define LOAD_TILE(cidx, buf)                                                  \
    do {                                                                      \
        const int kc = (cidx) * 32;                                           \
        _Pragma("unroll")                                                     \
        for (int i = 0; i < 2; i++) {                                         \
            const int lin = tid + i * 256;                                    \
            const int r = lin >> 2, ch = lin & 3;                             \
            cp_async16(sA[buf] + r * 80 + ch * 16,                            \
                       Ab + (size_t)r * 512 + kc + ch * 8);                   \
            cp_async16(sB[buf] + r * 80 + ch * 16,                            \
                       Bb + (size_t)r * 512 + kc + ch * 8);                   \
        }                                                                     \
    } while (0)

    LOAD_TILE(0, 0);
    CP_COMMIT();

    const uint32_t a_off =
        (uint32_t)(warp_m * 64 + (lane & 15)) * 80 + ((lane >> 4) << 4);
    const uint32_t b_off =
        (uint32_t)(warp_n * 32 + ((lane >> 4) << 3) + (lane & 7)) * 80 +
        (((lane >> 3) & 1) << 4);

    for (int c = 0; c < 16; c++) {
        const int buf = c & 1;
        if (c < 15) {
            LOAD_TILE(c + 1, buf ^ 1);
            CP_COMMIT();
            CP_WAIT(1);
        } else {
            CP_WAIT(0);
        }
        __syncthreads();

#pragma unroll
        for (int ks = 0; ks < 2; ks++) {
            uint32_t a[4][4], b[4][2];
#pragma unroll
            for (int mf = 0; mf < 4; mf++)
                ldsm_x4(a[mf], sA[buf] + a_off + mf * (16 * 80) + ks * 32);
#pragma unroll
            for (int g = 0; g < 2; g++) {
                uint32_t r[4];
                ldsm_x4(r, sB[buf] + b_off + g * (16 * 80) + ks * 32);
                b[g * 2][0] = r[0]; b[g * 2][1] = r[1];
                b[g * 2 + 1][0] = r[2]; b[g * 2 + 1][1] = r[3];
            }
#pragma unroll
            for (int mf = 0; mf < 4; mf++)
#pragma unroll
                for (int nf = 0; nf < 4; nf++)
                    mma_f16(acc[mf][nf], a[mf], b[nf]);
        }
        __syncthreads();
    }

    // epilogue: c0,c1 -> (row gid, col 2tig..), c2,c3 -> row gid+8
    const int erow = warp_m * 64 + (lane >> 2);
    const int ecol = warp_n * 32 + (lane & 3) * 2;
#pragma unroll
    for (int nf = 0; nf < 4; nf++) {
        const int col = bcol + ecol + nf * 8;
        const float2 bv = *(const float2*)(bias + col);
#pragma unroll
        for (int mf = 0; mf < 4; mf++) {
            float x0 = acc[mf][nf][0] + bv.x;
            float x1 = acc[mf][nf][1] + bv.y;
            float x2 = acc[mf][nf][2] + bv.x;
            float x3 = acc[mf][nf][3] + bv.y;
            if (do_gelu) {
                x0 = gelu_exact(x0); x1 = gelu_exact(x1);
                x2 = gelu_exact(x2); x3 = gelu_exact(x3);
            }
            const int r0 = brow + erow + mf * 16;
            *(__half2*)(C + (size_t)r0 * N + col) = __floats2half2_rn(x0, x1);
            *(__half2*)(C + (size_t)(r0 + 8) * N + col) =
                __floats2half2_rn(x2, x3);
        }
    }
}

// ---------------- build h1: smem-cached correction weights ------------------
__global__ void __launch_bounds__(256) build_h1_kernel(
    const float* __restrict__ pw1, const float* __restrict__ fw1,
    const int* __restrict__ perm_idx, int step)
{
    __shared__ float wc[24][512];
    const int tid = threadIdx.x;
#pragma unroll
    for (int i = 0; i < 12; i++) {
        const int lin = tid + i * 256;
        const int row = lin >> 7;
        const int c4 = (lin & 127) << 2;
        const float* src = (row < 9) ? (pw1 + (512 + row) * 512 + c4)
                                     : (fw1 + (512 + row - 9) * 512 + c4);
        *(float4*)&wc[row][c4] = *(const float4*)src;
    }
    __syncthreads();

    const int n0 = tid * 2;
#pragma unroll 1
    for (int r = 0; r < 8; r++) {
        const int b = blockIdx.x * 8 + r;
        const int ridx = c_perms[__ldg(&perm_idx[b])][step];
        float ps[6], fs[12];
#pragma unroll
        for (int j = 0; j < 6; j++) ps[j] = __ldg(&g_pres_state[b * 6 + j]);
#pragma unroll
        for (int j = 0; j < 12; j++) fs[j] = __ldg(&g_full_state[b * 12 + j]);

        float2 hp = __half22float2(*(const __half2*)&g_base_p[b * 512 + n0]);
#pragma unroll
        for (int j = 0; j < 6; j++) {
            const float2 w = *(const float2*)&wc[j][n0];
            hp.x = fmaf(ps[j], w.x, hp.x);
            hp.y = fmaf(ps[j], w.y, hp.y);
        }
        {
            const float2 w = *(const float2*)&wc[6 + ridx][n0];
            hp.x += w.x; hp.y += w.y;
        }
        hp.x = gelu_exact(hp.x); hp.y = gelu_exact(hp.y);
        *(__half2*)&g_h1_p[b * 512 + n0] = __floats2half2_rn(hp.x, hp.y);

        float2 hf = __half22float2(*(const __half2*)&g_base_f[b * 512 + n0]);
#pragma unroll
        for (int j = 0; j < 12; j++) {
            const float2 w = *(const float2*)&wc[9 + j][n0];
            hf.x = fmaf(fs[j], w.x, hf.x);
            hf.y = fmaf(fs[j], w.y, hf.y);
        }
        {
            const float2 w = *(const float2*)&wc[21 + ridx][n0];
            hf.x += w.x; hf.y += w.y;
        }
        hf.x = gelu_exact(hf.x); hf.y = gelu_exact(hf.y);
        *(__half2*)&g_h1_f[b * 512 + n0] = __floats2half2_rn(hf.x, hf.y);
    }
}

// ---------------- head (3rd layer dots) + losses + state update -------------
__global__ void __launch_bounds__(256) head_update_kernel(
    const float* __restrict__ pw3, const float* __restrict__ pb3,
    const float* __restrict__ fw3, const float* __restrict__ fb3,
    const float* __restrict__ freq, const float* __restrict__ pres,
    const float* __restrict__ enrich, const int* __restrict__ perm_idx,
    const int* __restrict__ round_mask, float* __restrict__ out, int step)
{
    __shared__ float blk[4];
    const int tid = threadIdx.x;
    const int lane = tid & 31;
    const int w = tid >> 5;
    if (tid < 4) blk[tid] = 0.f;
    __syncthreads();

    const int b = blockIdx.x * 8 + w;
    float pp = 0.f, pf = 0.f, pe = 0.f;
    const __half2* hp = (const __half2*)(g_h2_p + b * 256);
    const __half2* hf = (const __half2*)(g_h2_f + b * 512);

#pragma unroll
    for (int m = lane; m < 128; m += 32) {
        const float2 v = __half22float2(hp[m]);
        const float2 wv = *(const float2*)&pw3[2 * m];
        pp = fmaf(v.x, wv.x, pp);
        pp = fmaf(v.y, wv.y, pp);
    }
#pragma unroll
    for (int m = lane; m < 256; m += 32) {
        const float2 v = __half22float2(hf[m]);
        const float4 f3 = *(const float4*)&fw3[4 * m];
        pf = fmaf(v.x, f3.x, pf);
        pe = fmaf(v.x, f3.y, pe);
        pf = fmaf(v.y, f3.z, pf);
        pe = fmaf(v.y, f3.w, pe);
    }
#pragma unroll
    for (int o = 16; o > 0; o >>= 1) {
        pp += __shfl_xor_sync(0xffffffffu, pp, o);
        pf += __shfl_xor_sync(0xffffffffu, pf, o);
        pe += __shfl_xor_sync(0xffffffffu, pe, o);
    }

    if (lane == 0) {
        pp += pb3[0];
        pf += fb3[0];
        pe += fb3[1];
        const int ridx = c_perms[perm_idx[b]][step];
        const float m = (float)round_mask[b * 3 + ridx];
        const float gt_f = freq[b * 3 + ridx];
        const float gt_p = pres[b * 3 + ridx];
        const float gt_e = enrich[b * 3 + ridx];

        const float dlf = (pf - gt_f) * (pf - gt_f) * m;
        const float bce = fmaxf(pp, 0.f) - pp * gt_p + log1pf(expf(-fabsf(pp)));
        const float dlp = bce * m;
        const float dle = (pe - gt_e) * (pe - gt_e) * m;

        const bool msk = m > 0.5f;
        const float act_f = msk ? fminf(fmaxf(pf, -10.f), 10.f) : gt_f;
        const float act_p = msk ? (1.f / (1.f + expf(-pp))) : gt_p;
        const float act_e = msk ? fminf(fmaxf(pe, -100.f), 100.f) : gt_e;

        g_pres_state[b * 6 + 2 * ridx + 0] = act_p;
        g_pres_state[b * 6 + 2 * ridx + 1] = 1.f;
        g_full_state[b * 12 + 4 * ridx + 0] = act_f;
        g_full_state[b * 12 + 4 * ridx + 1] = act_p;
        g_full_state[b * 12 + 4 * ridx + 2] = act_e;
        g_full_state[b * 12 + 4 * ridx + 3] = 1.f;

        out[3 + b * 3 + ridx] = act_f;
        out[3 + 3 * BB + b * 3 + ridx] = act_p;
        out[3 + 6 * BB + b * 3 + ridx] = act_e;

        atomicAdd(&blk[0], dlf);
        atomicAdd(&blk[1], dlp);
        atomicAdd(&blk[2], dle);
        atomicAdd(&blk[3], m);
    }
    __syncthreads();
    if (tid < 4) atomicAdd(&g_losses[tid], blk[tid]);
}

__global__ void finalize_kernel(float* __restrict__ out) {
    if (threadIdx.x == 0 && blockIdx.x == 0) {
        const float nm = g_losses[3] + 1e-8f;
        out[0] = g_losses[0] / nm;
        out[1] = g_losses[1] / nm;
        out[2] = g_losses[2] / nm;
    }
}

// ---------------- launcher --------------------------------------------------
extern "C" void kernel_launch(void* const* d_in, const int* in_sizes, int n_in,
                              void* d_out, int out_size)
{
    const float* seq      = (const float*)d_in[0];
    const float* freq     = (const float*)d_in[1];
    const float* pres     = (const float*)d_in[2];
    const float* enrich   = (const float*)d_in[3];
    const float* pw1      = (const float*)d_in[4];
    const float* pb1      = (const float*)d_in[5];
    const float* pw2      = (const float*)d_in[6];
    const float* pb2      = (const float*)d_in[7];
    const float* pw3      = (const float*)d_in[8];
    const float* pb3      = (const float*)d_in[9];
    const float* fw1      = (const float*)d_in[10];
    const float* fb1      = (const float*)d_in[11];
    const float* fw2      = (const float*)d_in[12];
    const float* fb2      = (const float*)d_in[13];
    const float* fw3      = (const float*)d_in[14];
    const float* fb3      = (const float*)d_in[15];
    const int*   perm_idx = (const int*)d_in[16];
    const int*   rmask    = (const int*)d_in[17];
    float* out = (float*)d_out;

    __half *seq_h, *base_p, *base_f, *h1_p, *h1_f, *h2_p, *h2_f;
    __half *wt_p1, *wt_f1, *wt_p2, *wt_f2;
    cudaGetSymbolAddress((void**)&seq_h, g_seq_h);
    cudaGetSymbolAddress((void**)&base_p, g_base_p);
    cudaGetSymbolAddress((void**)&base_f, g_base_f);
    cudaGetSymbolAddress((void**)&h1_p, g_h1_p);
    cudaGetSymbolAddress((void**)&h1_f, g_h1_f);
    cudaGetSymbolAddress((void**)&h2_p, g_h2_p);
    cudaGetSymbolAddress((void**)&h2_f, g_h2_f);
    cudaGetSymbolAddress((void**)&wt_p1, g_wt_p1);
    cudaGetSymbolAddress((void**)&wt_f1, g_wt_f1);
    cudaGetSymbolAddress((void**)&wt_p2, g_wt_p2);
    cudaGetSymbolAddress((void**)&wt_f2, g_wt_f2);

    init_kernel<<<256, 256>>>();
    convert_seq_kernel<<<BB * 512 / (256 * 8), 256>>>(seq, seq_h);

    transpose_kernel<<<dim3(16, 16), dim3(32, 8)>>>(pw1, wt_p1, 512);
    transpose_kernel<<<dim3(16, 16), dim3(32, 8)>>>(fw1, wt_f1, 512);
    transpose_kernel<<<dim3(8, 16), dim3(32, 8)>>>(pw2, wt_p2, 256);
    transpose_kernel<<<dim3(16, 16), dim3(32, 8)>>>(fw2, wt_f2, 512);

    // step-invariant base: seq @ W1[:512] + b1 (NO gelu)
    gemm_h<<<dim3(4, 128), 256>>>(seq_h, wt_p1, pb1, base_p, 512, 0);
    gemm_h<<<dim3(4, 128), 256>>>(seq_h, wt_f1, fb1, base_f, 512, 0);

    for (int step = 0; step < 3; step++) {
        build_h1_kernel<<<BB / 8, 256>>>(pw1, fw1, perm_idx, step);
        gemm_h<<<dim3(2, 128), 256>>>(h1_p, wt_p2, pb2, h2_p, 256, 1);
        gemm_h<<<dim3(4, 128), 256>>>(h1_f, wt_f2, fb2, h2_f, 512, 1);
        head_update_kernel<<<BB / 8, 256>>>(pw3, pb3, fw3, fb3, freq, pres,
                                            enrich, perm_idx, rmask, out, step);
    }

    finalize_kernel<<<1, 32>>>(out);
}